// round 1
// baseline (speedup 1.0000x reference)
#include <cuda_runtime.h>
#include <math.h>

// Problem shape (fixed by the dataset)
#define B_DIM 256
#define K_DIM 512
#define D_DIM 1024
#define INV_T 14.2857142857142857f   // 1/0.07

// Scratch (no allocations allowed)
__device__ double g_pos;                 // sum over all (b,k) of exp(bg_logit/T)
__device__ double g_fg;                  // sum over b of exp(fg_logit/T)
__device__ float  g_inv_norm[B_DIM];

__global__ void init_kernel() {
    g_pos = 0.0;
    g_fg  = 0.0;
}

// One block per batch row: compute 1/||bg_img[b]|| and the fg logit contribution.
__global__ void norm_fg_kernel(const float* __restrict__ bg_img,
                               const float* __restrict__ fg_pro) {
    const int b = blockIdx.x;
    const int t = threadIdx.x;            // 256 threads, D/4 = 256 float4 per row
    const float4* q4 = reinterpret_cast<const float4*>(bg_img + (size_t)b * D_DIM);
    const float4* f4 = reinterpret_cast<const float4*>(fg_pro + (size_t)b * D_DIM);
    float4 q = q4[t];
    float4 f = f4[t];
    float ss = q.x*q.x + q.y*q.y + q.z*q.z + q.w*q.w;
    float fd = q.x*f.x + q.y*f.y + q.z*f.z + q.w*f.w;

    #pragma unroll
    for (int o = 16; o; o >>= 1) {
        ss += __shfl_xor_sync(0xFFFFFFFFu, ss, o);
        fd += __shfl_xor_sync(0xFFFFFFFFu, fd, o);
    }
    __shared__ float w_ss[8], w_fd[8];
    const int warp = t >> 5, lane = t & 31;
    if (lane == 0) { w_ss[warp] = ss; w_fd[warp] = fd; }
    __syncthreads();
    if (t == 0) {
        float tss = 0.f, tfd = 0.f;
        #pragma unroll
        for (int i = 0; i < 8; i++) { tss += w_ss[i]; tfd += w_fd[i]; }
        const float inv = 1.0f / sqrtf(tss);
        g_inv_norm[b] = inv;
        atomicAdd(&g_fg, (double)expf(tfd * inv * INV_T));
    }
}

// Main streaming kernel: grid (B, K/64), 256 threads = 8 warps.
// Each warp owns 8 consecutive k rows; the normalized query row lives in
// 32 registers per thread (lane l holds elements i*128 + l*4), so the hot
// loop is pure coalesced LDG.128 from bg_pro + FFMA + one shfl reduce.
__global__ __launch_bounds__(256)
void bg_logits_kernel(const float* __restrict__ bg_img,
                      const float* __restrict__ bg_pro) {
    const int b    = blockIdx.x;
    const int ky   = blockIdx.y;
    const int warp = threadIdx.x >> 5;
    const int lane = threadIdx.x & 31;

    const float inv = g_inv_norm[b];

    // Hoist normalized query row into registers: q[i] = row[i*128 + lane*4 .. +3]
    float4 q[8];
    const float4* qrow = reinterpret_cast<const float4*>(bg_img + (size_t)b * D_DIM);
    #pragma unroll
    for (int i = 0; i < 8; i++) {
        float4 v = qrow[i * 32 + lane];
        v.x *= inv; v.y *= inv; v.z *= inv; v.w *= inv;
        q[i] = v;
    }

    const int k0 = ky * 64 + warp * 8;
    const float4* prow =
        reinterpret_cast<const float4*>(bg_pro + ((size_t)b * K_DIM + k0) * D_DIM);

    double acc = 0.0;
    #pragma unroll
    for (int kk = 0; kk < 8; kk++) {
        const float4* p = prow + (size_t)kk * (D_DIM / 4);
        float s = 0.f;
        #pragma unroll
        for (int i = 0; i < 8; i++) {
            float4 pv = p[i * 32 + lane];
            s = fmaf(q[i].x, pv.x, s);
            s = fmaf(q[i].y, pv.y, s);
            s = fmaf(q[i].z, pv.z, s);
            s = fmaf(q[i].w, pv.w, s);
        }
        #pragma unroll
        for (int o = 16; o; o >>= 1) s += __shfl_xor_sync(0xFFFFFFFFu, s, o);
        if (lane == 0) acc += (double)expf(s * INV_T);
    }

    __shared__ double sacc[8];
    if (lane == 0) sacc[warp] = acc;
    __syncthreads();
    if (threadIdx.x == 0) {
        double t = 0.0;
        #pragma unroll
        for (int i = 0; i < 8; i++) t += sacc[i];
        atomicAdd(&g_pos, t);
    }
}

// out = -log(pos/neg) = log(neg/pos) = log1p(K*F/S), computed in double.
__global__ void finalize_kernel(float* __restrict__ out) {
    const double S = g_pos;   // sum_{b,k} exp
    const double F = g_fg;    // sum_b exp(fg)
    out[0] = (float)log1p(F * (double)K_DIM / S);
}

extern "C" void kernel_launch(void* const* d_in, const int* in_sizes, int n_in,
                              void* d_out, int out_size) {
    const float* bg_img = (const float*)d_in[0];   // [B, D]
    const float* fg_pro = (const float*)d_in[1];   // [B, D]
    const float* bg_pro = (const float*)d_in[2];   // [B, K, D]
    float* out = (float*)d_out;

    init_kernel<<<1, 1>>>();
    norm_fg_kernel<<<B_DIM, 256>>>(bg_img, fg_pro);
    dim3 grid(B_DIM, K_DIM / 64);
    bg_logits_kernel<<<grid, 256>>>(bg_img, bg_pro);
    finalize_kernel<<<1, 1>>>(out);
}